// round 13
// baseline (speedup 1.0000x reference)
#include <cuda_runtime.h>
#include <cuda_bf16.h>

// SMPL forward kinematics, algebraically simplified:
//   out[b,j,:] = sum over chain ancestors a of j of delta_a,
//   delta_a    = R[b, parent(a)] @ offp_a   (delta_root = 0),
//   offp       = (off.y, off.z, off.x)
// (G is a permutation; the G / G^T einsums cancel through the chain.)
//
// vs R3 (55.8us, DRAM 31.5%, occ 22.4%, regs 124):
//  - FK parallelized across joints: independent per-joint delta phase (all
//    128 threads) + per-joint ancestor-sum fused with the global store.
//    Ancestor sums use a zero-padded flat table summed with a FIXED 8-entry
//    fully-unrolled loop (delta_0 == 0 makes padding free) -> no divergence,
//    8 independent LDS in flight.
//  - Offsets + topology baked as __constant__ (fixed by the problem).
//  - ~30 regs, 18.56 KB smem -> ~11 CTAs/SM (~69% occ), stage loop fully
//    unrolled (27 LDG batched per warp) => DRAM latency hidden.

#define BPB      16    // bodies per block
#define THREADS  128
#define SPITCH   217   // 216 floats/body + 1 pad (coprime with 32 banks)
#define OPITCH   73    // 72 floats/body + 1 pad (coprime with 32 banks)

__constant__ int c_par[24] = {0, 0, 1, 2, 3, 0, 5, 6, 7, 0, 9, 10, 11, 12,
                              11, 14, 15, 16, 17, 11, 19, 20, 21, 22};
// Non-root ancestors of each joint, zero-padded (delta_0 == 0, so the pad
// entries contribute nothing; we always sum all 8).
__constant__ signed char c_anc[24][8] = {
    {0,0,0,0,0,0,0,0},                   // 0: none
    {1,0,0,0,0,0,0,0},                   // 1
    {2,1,0,0,0,0,0,0},                   // 2
    {3,2,1,0,0,0,0,0},                   // 3
    {4,3,2,1,0,0,0,0},                   // 4
    {5,0,0,0,0,0,0,0},                   // 5
    {6,5,0,0,0,0,0,0},                   // 6
    {7,6,5,0,0,0,0,0},                   // 7
    {8,7,6,5,0,0,0,0},                   // 8
    {9,0,0,0,0,0,0,0},                   // 9
    {10,9,0,0,0,0,0,0},                  // 10
    {11,10,9,0,0,0,0,0},                 // 11
    {12,11,10,9,0,0,0,0},                // 12
    {13,12,11,10,9,0,0,0},               // 13
    {14,11,10,9,0,0,0,0},                // 14
    {15,14,11,10,9,0,0,0},               // 15
    {16,15,14,11,10,9,0,0},              // 16
    {17,16,15,14,11,10,9,0},             // 17
    {18,17,16,15,14,11,10,9},            // 18
    {19,11,10,9,0,0,0,0},                // 19
    {20,19,11,10,9,0,0,0},               // 20
    {21,20,19,11,10,9,0,0},              // 21
    {22,21,20,19,11,10,9,0},             // 22
    {23,22,21,20,19,11,10,9}             // 23
};
// Permuted offsets offp_j = (off.y, off.z, off.x); root unused (delta_0 = 0).
__constant__ float c_ox[24] = {0.0f, 0.0372f, 0.0276f, -0.0094f, 0.0261f, -0.0383f,
                               -0.0275f, 0.0121f, -0.0221f, 0.0028f, 0.0028f, -0.0014f,
                               -0.0085f, 0.0064f, 0.0455f, 0.078f, 0.1621f, 0.1687f,
                               0.055f, -0.0527f, -0.0719f, -0.1651f, -0.1708f, -0.0563f};
__constant__ float c_oy[24] = {0.0f, -0.0522f, -0.2453f, -0.271f, -0.0383f, -0.0575f,
                               -0.2436f, -0.2666f, -0.0394f, 0.079f, 0.0876f, 0.0356f,
                               0.1343f, 0.0565f, 0.0724f, 0.0287f, -0.0099f, 0.0081f,
                               -0.0068f, 0.0714f, 0.0297f, -0.0091f, 0.0043f, -0.0055f};
__constant__ float c_oz[24] = {0.0f, -0.0112f, 0.0051f, -0.0238f, 0.0775f, -0.0086f,
                               -0.0031f, -0.0219f, 0.0827f, -0.0244f, 0.017f, 0.0018f,
                               -0.0212f, 0.032f, -0.012f, -0.0121f, -0.0146f, -0.0047f,
                               -0.0099f, -0.015f, -0.0054f, -0.0198f, -0.0038f, -0.0064f};

__global__ void __launch_bounds__(THREADS, 11)
smpl_skel_kernel(const float* __restrict__ R,
                 float* __restrict__ out,
                 int B)
{
    extern __shared__ float s[];          // [BPB*SPITCH] matrices | [BPB*OPITCH] deltas
    float* sdelta = s + BPB * SPITCH;

    const int tid  = threadIdx.x;
    const int base = blockIdx.x * BPB;
    const int nb   = min(BPB, B - base);

    // ---- Phase 1: stage matrices. Coalesced scalar LDG, lane-stride-1 STS. ----
    const float* ing = R + (size_t)base * 216;
    if (nb == BPB) {
        #pragma unroll
        for (int k = 0; k < (BPB * 216) / THREADS; ++k) {   // 27 iters, LDGs batched
            int i    = tid + k * THREADS;
            int body = i / 216;
            int e    = i - body * 216;
            s[body * SPITCH + e] = ing[i];
        }
    } else {
        for (int i = tid; i < nb * 216; i += THREADS) {
            int body = i / 216;
            int e    = i - body * 216;
            s[body * SPITCH + e] = ing[i];
        }
    }
    __syncthreads();

    // ---- Phase 2: per-joint deltas (independent), all threads. ----
    const int nitems = nb * 24;           // 384 for a full block
    #pragma unroll 3
    for (int i = tid; i < nitems; i += THREADS) {
        int body = i / 24;
        int j    = i - body * 24;
        float dx = 0.0f, dy = 0.0f, dz = 0.0f;
        if (j != 0) {
            const float* Rp = s + body * SPITCH + c_par[j] * 9;
            const float ox = c_ox[j], oy = c_oy[j], oz = c_oz[j];
            dx = fmaf(Rp[0], ox, fmaf(Rp[1], oy, Rp[2] * oz));
            dy = fmaf(Rp[3], ox, fmaf(Rp[4], oy, Rp[5] * oz));
            dz = fmaf(Rp[6], ox, fmaf(Rp[7], oy, Rp[8] * oz));
        }
        float* d = sdelta + body * OPITCH + j * 3;
        d[0] = dx; d[1] = dy; d[2] = dz;
    }
    __syncthreads();

    // ---- Phase 3: fixed 8-term ancestor sums (no divergence), fused STG. ----
    #pragma unroll 3
    for (int i = tid; i < nitems; i += THREADS) {
        int body = i / 24;
        int j    = i - body * 24;
        const float* d = sdelta + body * OPITCH;
        float ax = 0.0f, ay = 0.0f, az = 0.0f;
        #pragma unroll
        for (int t = 0; t < 8; ++t) {     // padded entries hit delta_0 == 0
            int a = c_anc[j][t];
            ax += d[a * 3 + 0];
            ay += d[a * 3 + 1];
            az += d[a * 3 + 2];
        }
        float* o = out + (size_t)(base + body) * 72 + j * 3;
        o[0] = ax; o[1] = ay; o[2] = az;
    }
}

extern "C" void kernel_launch(void* const* d_in, const int* in_sizes, int n_in,
                              void* d_out, int out_size)
{
    const float* R = (const float*)d_in[0];   // (B, 24, 3, 3) fp32
    float* out     = (float*)d_out;           // (B, 24, 3) fp32

    const int B    = in_sizes[0] / 216;
    const int grid = (B + BPB - 1) / BPB;     // 8192 blocks @ B=131072
    const size_t smem = (size_t)(BPB * SPITCH + BPB * OPITCH) * sizeof(float); // 18,560 B

    smpl_skel_kernel<<<grid, THREADS, smem>>>(R, out, B);
}